// round 13
// baseline (speedup 1.0000x reference)
#include <cuda_runtime.h>
#include <cuda_fp16.h>

#define N_NODES 50000
#define IN_CH   128
#define HID     32
#define HEADS   4
#define HO      128
#define N_E     800000
#define N_ET    850000

// ---------------- scratch ----------------------------------------------------
__device__ __half2 g_h1h[N_NODES*64];    // layer1 raw features, fp16
__device__ float  g_as1[N_NODES*HEADS];
__device__ float  g_ad1[N_NODES*HEADS];
__device__ __half g_h2h[N_NODES*HID];    // layer2 raw features, fp16
__device__ float  g_as2[N_NODES];
__device__ float  g_ad2[N_NODES];
// CSR
__device__ int g_deg [N_NODES];
__device__ int g_off [N_NODES];
__device__ int g_pos [N_NODES];
__device__ int g_srcs[N_ET];

__device__ __forceinline__ unsigned f2tf32(float f) {
    unsigned r; asm("cvt.rna.tf32.f32 %0, %1;" : "=r"(r) : "f"(f)); return r;
}

// ---------------- CSR build --------------------------------------------------
__global__ void k_zero_deg() {
    int i = blockIdx.x * blockDim.x + threadIdx.x;
    if (i < N_NODES) g_deg[i] = 0;
}

__global__ void k_hist(const int* __restrict__ dst_idx) {
    int e = blockIdx.x * blockDim.x + threadIdx.x;
    if (e >= N_ET) return;
    int dst = (e < N_E) ? __ldg(&dst_idx[e]) : (e - N_E);
    atomicAdd(&g_deg[dst], 1);
}

__global__ __launch_bounds__(1024) void k_scan() {
    __shared__ int ssum[1024];
    int t = threadIdx.x;
    const int PER = (N_NODES + 1023) / 1024;
    int base = t * PER;
    int s = 0;
    for (int i = 0; i < PER; i++) {
        int idx = base + i;
        if (idx < N_NODES) s += g_deg[idx];
    }
    ssum[t] = s;
    __syncthreads();
    for (int d = 1; d < 1024; d <<= 1) {
        int add = (t >= d) ? ssum[t - d] : 0;
        __syncthreads();
        ssum[t] += add;
        __syncthreads();
    }
    int off = ssum[t] - s;
    for (int i = 0; i < PER; i++) {
        int idx = base + i;
        if (idx < N_NODES) {
            int d = g_deg[idx];
            g_off[idx] = off;
            g_pos[idx] = off;
            off += d;
        }
    }
}

__global__ void k_scatter(const int* __restrict__ src_idx, const int* __restrict__ dst_idx) {
    int e = blockIdx.x * blockDim.x + threadIdx.x;
    if (e >= N_ET) return;
    int src, dst;
    if (e < N_E) { src = __ldg(&src_idx[e]); dst = __ldg(&dst_idx[e]); }
    else         { src = dst = e - N_E; }
    int p = atomicAdd(&g_pos[dst], 1);
    g_srcs[p] = src;
}

// ---------------- GEMM1 (tf32 tensor cores): h1 = x @ W1 + alphas ------------
// Block = 128 threads (4 warps), tile = 64 rows. Warp w computes rows
// [tile*64 + w*16, +16) x 128 cols via m16n8k8 tf32 mma.
#define G1_TILEROWS 64
#define G1_TILES    ((N_NODES + G1_TILEROWS - 1) / G1_TILEROWS)   // 782
#define G1_BLOCKS   296
#define G1_SMEM     ((128 + 64) * 132 * 4)

__global__ __launch_bounds__(128) void k_gemm1_mma(
        const float* __restrict__ x, const float* __restrict__ W1,
        const float* __restrict__ a_src, const float* __restrict__ a_dst)
{
    extern __shared__ float sm[];
    float* Ws = sm;               // [128][132] tf32 bits
    float* xs = sm + 128*132;     // [64][132]  tf32 bits

    int t = threadIdx.x, lane = t & 31, w = t >> 5;
    int gr = lane >> 2, gc = lane & 3;

    // stage W1 (tf32-converted) once
    for (int i = t; i < 128*128/4; i += 128) {
        float4 v = ((const float4*)W1)[i];
        int r = i >> 5;          // 32 float4 per 128-col row
        int c = (i & 31) * 4;
        float* dstp = &Ws[r*132 + c];
        dstp[0] = __uint_as_float(f2tf32(v.x));
        dstp[1] = __uint_as_float(f2tf32(v.y));
        dstp[2] = __uint_as_float(f2tf32(v.z));
        dstp[3] = __uint_as_float(f2tf32(v.w));
    }
    __syncthreads();

    for (int tile = blockIdx.x; tile < G1_TILES; tile += G1_BLOCKS) {
        int rowbase = tile * G1_TILEROWS;

        // stage 64 x-rows (tf32), zero-pad beyond N_NODES
        for (int i = t; i < 64*128/4; i += 128) {
            int r = i >> 5;
            int c = (i & 31) * 4;
            int grow = rowbase + r;
            float* dstp = &xs[r*132 + c];
            if (grow < N_NODES) {
                float4 v = *(const float4*)&x[grow*128 + c];
                dstp[0] = __uint_as_float(f2tf32(v.x));
                dstp[1] = __uint_as_float(f2tf32(v.y));
                dstp[2] = __uint_as_float(f2tf32(v.z));
                dstp[3] = __uint_as_float(f2tf32(v.w));
            } else {
                dstp[0] = 0.f; dstp[1] = 0.f; dstp[2] = 0.f; dstp[3] = 0.f;
            }
        }
        __syncthreads();

        int warpRow = rowbase + w*16;
        if (warpRow < N_NODES) {
            float acc[16][4];
            #pragma unroll
            for (int j = 0; j < 16; j++) { acc[j][0]=acc[j][1]=acc[j][2]=acc[j][3]=0.f; }

            const float* xw = xs + (w*16)*132;
            #pragma unroll
            for (int kk = 0; kk < 16; kk++) {
                int k0 = kk*8;
                unsigned a0 = __float_as_uint(xw[ gr     *132 + k0 + gc    ]);
                unsigned a1 = __float_as_uint(xw[(gr+8)  *132 + k0 + gc    ]);
                unsigned a2 = __float_as_uint(xw[ gr     *132 + k0 + gc + 4]);
                unsigned a3 = __float_as_uint(xw[(gr+8)  *132 + k0 + gc + 4]);
                #pragma unroll
                for (int j = 0; j < 16; j++) {
                    unsigned b0 = __float_as_uint(Ws[(k0 + gc    )*132 + 8*j + gr]);
                    unsigned b1 = __float_as_uint(Ws[(k0 + gc + 4)*132 + 8*j + gr]);
                    asm volatile(
                        "mma.sync.aligned.m16n8k8.row.col.f32.tf32.tf32.f32 "
                        "{%0,%1,%2,%3}, {%4,%5,%6,%7}, {%8,%9}, {%0,%1,%2,%3};"
                        : "+f"(acc[j][0]), "+f"(acc[j][1]), "+f"(acc[j][2]), "+f"(acc[j][3])
                        : "r"(a0), "r"(a1), "r"(a2), "r"(a3), "r"(b0), "r"(b1));
                }
            }

            int row0 = warpRow + gr, row1 = row0 + 8;

            // store h1 fp16: c0/c1 are cols 8j+2gc, 8j+2gc+1
            #pragma unroll
            for (int j = 0; j < 16; j++) {
                g_h1h[row0*64 + 4*j + gc] = __floats2half2_rn(acc[j][0], acc[j][1]);
                g_h1h[row1*64 + 4*j + gc] = __floats2half2_rn(acc[j][2], acc[j][3]);
            }

            // alphas per head (head h covers n-tiles 4h..4h+3)
            #pragma unroll
            for (int h = 0; h < 4; h++) {
                float s0=0.f, s1=0.f, d0=0.f, d1=0.f;
                #pragma unroll
                for (int jj = 0; jj < 4; jj++) {
                    int j = h*4 + jj;
                    float2 av = __ldg((const float2*)a_src + 4*j + gc);
                    float2 dv = __ldg((const float2*)a_dst + 4*j + gc);
                    s0 += acc[j][0]*av.x + acc[j][1]*av.y;
                    s1 += acc[j][2]*av.x + acc[j][3]*av.y;
                    d0 += acc[j][0]*dv.x + acc[j][1]*dv.y;
                    d1 += acc[j][2]*dv.x + acc[j][3]*dv.y;
                }
                s0 += __shfl_xor_sync(0xffffffffu, s0, 1);
                s0 += __shfl_xor_sync(0xffffffffu, s0, 2);
                s1 += __shfl_xor_sync(0xffffffffu, s1, 1);
                s1 += __shfl_xor_sync(0xffffffffu, s1, 2);
                d0 += __shfl_xor_sync(0xffffffffu, d0, 1);
                d0 += __shfl_xor_sync(0xffffffffu, d0, 2);
                d1 += __shfl_xor_sync(0xffffffffu, d1, 1);
                d1 += __shfl_xor_sync(0xffffffffu, d1, 2);
                if (gc == 0) {
                    g_as1[row0*4 + h] = s0; g_as1[row1*4 + h] = s1;
                    g_ad1[row0*4 + h] = d0; g_ad1[row1*4 + h] = d1;
                }
            }
        }
        __syncthreads();   // protect xs before next tile overwrites
    }
}

// ---------------- fused edge pass 1 + GEMM2 (half-warp dual-src) -------------
// warp per dst node. lanes 0-15 process even-index srcs, 16-31 odd.
// lane owns 8 channels (uint4 of fp16); head = (lane&15)>>2.
__global__ __launch_bounds__(256) void k_edge1_fused(
        const float* __restrict__ b1, const float* __restrict__ W2,
        const float* __restrict__ a_src2, const float* __restrict__ a_dst2)
{
    __shared__ float WsT[32][132];   // WsT[c][k] = W2[k*32+c]
    __shared__ float xsh[8][128];

    int t = threadIdx.x, lane = t & 31, w = t >> 5;
    int g = lane >> 4, lc = lane & 15;
    int head = lc >> 2;

    for (int i = t; i < 128*32/4; i += 256) {
        float4 v = ((const float4*)W2)[i];
        int k = i >> 3;
        int c = (i & 7) * 4;
        WsT[c+0][k] = v.x; WsT[c+1][k] = v.y; WsT[c+2][k] = v.z; WsT[c+3][k] = v.w;
    }
    __syncthreads();

    int n = (blockIdx.x * blockDim.x + t) >> 5;
    if (n >= N_NODES) return;
    int beg = g_off[n];
    int deg = g_deg[n];
    float ad = g_ad1[n*4 + head];

    float acc[8];
    #pragma unroll
    for (int c = 0; c < 8; c++) acc[c] = 0.f;
    float den = 0.f;

    for (int base = 0; base < deg; base += 32) {
        int rem = deg - base;
        int cnt = rem < 32 ? rem : 32;
        int s_l = (lane < cnt) ? __ldg(&g_srcs[beg + base + lane]) : 0;

        int half = cnt >> 1;             // pairs fully valid for both groups
        int k = 0;
        for (; k + 4 <= half; k += 4) {
            int ss[4]; float ee[4]; uint4 rr[4];
            #pragma unroll
            for (int u = 0; u < 4; u++)
                ss[u] = __shfl_sync(0xffffffffu, s_l, 2*(k+u) + g);
            #pragma unroll
            for (int u = 0; u < 4; u++) {
                ee[u] = __ldg(&g_as1[ss[u]*4 + head]) + ad;
                rr[u] = __ldg((const uint4*)&g_h1h[ss[u]*64] + lc);
            }
            #pragma unroll
            for (int u = 0; u < 4; u++) {
                float e = ee[u];
                e = e>0.f ? e : 0.2f*e;
                float wg = __expf(e);
                den += wg;
                float2 f0 = __half22float2(*(__half2*)&rr[u].x);
                float2 f1 = __half22float2(*(__half2*)&rr[u].y);
                float2 f2 = __half22float2(*(__half2*)&rr[u].z);
                float2 f3 = __half22float2(*(__half2*)&rr[u].w);
                acc[0] += wg*f0.x; acc[1] += wg*f0.y;
                acc[2] += wg*f1.x; acc[3] += wg*f1.y;
                acc[4] += wg*f2.x; acc[5] += wg*f2.y;
                acc[6] += wg*f3.x; acc[7] += wg*f3.y;
            }
        }
        int kmax = (cnt + 1) >> 1;       // max items over both groups
        for (; k < kmax; k++) {
            int j = 2*k + g;
            bool valid = j < cnt;
            int s = __shfl_sync(0xffffffffu, s_l, valid ? j : 0);
            if (valid) {
                float e = __ldg(&g_as1[s*4 + head]) + ad;
                e = e>0.f ? e : 0.2f*e;
                float wg = __expf(e);
                den += wg;
                uint4 r = __ldg((const uint4*)&g_h1h[s*64] + lc);
                float2 f0 = __half22float2(*(__half2*)&r.x);
                float2 f1 = __half22float2(*(__half2*)&r.y);
                float2 f2 = __half22float2(*(__half2*)&r.z);
                float2 f3 = __half22float2(*(__half2*)&r.w);
                acc[0] += wg*f0.x; acc[1] += wg*f0.y;
                acc[2] += wg*f1.x; acc[3] += wg*f1.y;
                acc[4] += wg*f2.x; acc[5] += wg*f2.y;
                acc[6] += wg*f3.x; acc[7] += wg*f3.y;
            }
        }
    }

    // combine the two half-warp groups
    den += __shfl_xor_sync(0xffffffffu, den, 16);
    #pragma unroll
    for (int c = 0; c < 8; c++) acc[c] += __shfl_xor_sync(0xffffffffu, acc[c], 16);

    // normalize + b1 + ELU -> hact row in smem (lanes of group 0 write)
    if (g == 0) {
        float dinv = 1.f / den;
        float4 b0 = __ldg((const float4*)b1 + 2*lc);
        float4 b1v = __ldg((const float4*)b1 + 2*lc + 1);
        float v0 = acc[0]*dinv + b0.x, v1 = acc[1]*dinv + b0.y;
        float v2 = acc[2]*dinv + b0.z, v3 = acc[3]*dinv + b0.w;
        float v4 = acc[4]*dinv + b1v.x, v5 = acc[5]*dinv + b1v.y;
        float v6 = acc[6]*dinv + b1v.z, v7 = acc[7]*dinv + b1v.w;
        v0 = v0>0.f?v0:expm1f(v0); v1 = v1>0.f?v1:expm1f(v1);
        v2 = v2>0.f?v2:expm1f(v2); v3 = v3>0.f?v3:expm1f(v3);
        v4 = v4>0.f?v4:expm1f(v4); v5 = v5>0.f?v5:expm1f(v5);
        v6 = v6>0.f?v6:expm1f(v6); v7 = v7>0.f?v7:expm1f(v7);
        *(float4*)&xsh[w][8*lc    ] = make_float4(v0, v1, v2, v3);
        *(float4*)&xsh[w][8*lc + 4] = make_float4(v4, v5, v6, v7);
    }
    __syncwarp();

    // inline GEMM2: lane computes output column `lane`
    float acc2 = 0.f;
    #pragma unroll
    for (int k4 = 0; k4 < 32; k4++) {
        float4 wv = *(const float4*)&WsT[lane][k4*4];
        float4 xa = *(const float4*)&xsh[w][k4*4];
        acc2 += xa.x*wv.x + xa.y*wv.y + xa.z*wv.z + xa.w*wv.w;
    }
    g_h2h[n*32 + lane] = __float2half_rn(acc2);

    float s = acc2 * __ldg(&a_src2[lane]);
    float d = acc2 * __ldg(&a_dst2[lane]);
    #pragma unroll
    for (int off = 16; off; off >>= 1) {
        s += __shfl_down_sync(0xffffffffu, s, off);
        d += __shfl_down_sync(0xffffffffu, d, off);
    }
    if (lane == 0) { g_as2[n] = s; g_ad2[n] = d; }
}

// ---------------- edge pass 2 (half-warp dual-src), writes d_out -------------
// lane owns 2 channels (half2); lanes 0-15 even srcs, 16-31 odd srcs.
__global__ __launch_bounds__(256) void k_edge2_csr(float* __restrict__ out,
                                                   const float* __restrict__ b2)
{
    int t = threadIdx.x;
    int n = (blockIdx.x * blockDim.x + t) >> 5;
    int lane = t & 31;
    int g = lane >> 4, lc = lane & 15;
    if (n >= N_NODES) return;
    int beg = g_off[n];
    int deg = g_deg[n];
    float ad = g_ad2[n];

    float ax = 0.f, ay = 0.f, den = 0.f;

    for (int base = 0; base < deg; base += 32) {
        int rem = deg - base;
        int cnt = rem < 32 ? rem : 32;
        int s_l = (lane < cnt) ? __ldg(&g_srcs[beg + base + lane]) : 0;

        int half = cnt >> 1;
        int k = 0;
        for (; k + 4 <= half; k += 4) {
            int ss[4]; float ee[4]; __half2 hh[4];
            #pragma unroll
            for (int u = 0; u < 4; u++)
                ss[u] = __shfl_sync(0xffffffffu, s_l, 2*(k+u) + g);
            #pragma unroll
            for (int u = 0; u < 4; u++) {
                ee[u] = __ldg(&g_as2[ss[u]]) + ad;
                hh[u] = __ldg((const __half2*)&g_h2h[ss[u]*32] + lc);
            }
            #pragma unroll
            for (int u = 0; u < 4; u++) {
                float e = ee[u];
                e = e>0.f ? e : 0.2f*e;
                float wg = __expf(e);
                den += wg;
                float2 f = __half22float2(hh[u]);
                ax += wg*f.x; ay += wg*f.y;
            }
        }
        int kmax = (cnt + 1) >> 1;
        for (; k < kmax; k++) {
            int j = 2*k + g;
            bool valid = j < cnt;
            int s = __shfl_sync(0xffffffffu, s_l, valid ? j : 0);
            if (valid) {
                float e = __ldg(&g_as2[s]) + ad;
                e = e>0.f ? e : 0.2f*e;
                float wg = __expf(e);
                den += wg;
                float2 f = __half22float2(__ldg((const __half2*)&g_h2h[s*32] + lc));
                ax += wg*f.x; ay += wg*f.y;
            }
        }
    }

    den += __shfl_xor_sync(0xffffffffu, den, 16);
    ax  += __shfl_xor_sync(0xffffffffu, ax, 16);
    ay  += __shfl_xor_sync(0xffffffffu, ay, 16);

    if (g == 0) {
        float dinv = 1.f / den;
        float2 bb = __ldg((const float2*)b2 + lc);
        *(float2*)&out[n*32 + 2*lc] = make_float2(ax*dinv + bb.x, ay*dinv + bb.y);
    }
}

// ---------------- launch -----------------------------------------------------
extern "C" void kernel_launch(void* const* d_in, const int* in_sizes, int n_in,
                              void* d_out, int out_size)
{
    const float* x     = (const float*)d_in[0];
    const int*   ei    = (const int*)d_in[1];
    const float* W1    = (const float*)d_in[2];
    const float* asrc1 = (const float*)d_in[3];
    const float* adst1 = (const float*)d_in[4];
    const float* b1    = (const float*)d_in[5];
    const float* W2    = (const float*)d_in[6];
    const float* asrc2 = (const float*)d_in[7];
    const float* adst2 = (const float*)d_in[8];
    const float* b2    = (const float*)d_in[9];
    float* out = (float*)d_out;

    const int* src_idx = ei;
    const int* dst_idx = ei + N_E;

    static cudaStream_t s_side = nullptr;
    static cudaEvent_t ev_fork = nullptr, ev_join = nullptr;
    if (!s_side) {
        cudaStreamCreateWithFlags(&s_side, cudaStreamNonBlocking);
        cudaEventCreateWithFlags(&ev_fork, cudaEventDisableTiming);
        cudaEventCreateWithFlags(&ev_join, cudaEventDisableTiming);
    }

    cudaFuncSetAttribute(k_gemm1_mma, cudaFuncAttributeMaxDynamicSharedMemorySize, G1_SMEM);

    // fork: CSR build on side stream, gemm1 on main stream
    cudaEventRecord(ev_fork, 0);
    cudaStreamWaitEvent(s_side, ev_fork, 0);

    k_zero_deg<<<(N_NODES + 255)/256, 256, 0, s_side>>>();
    k_hist<<<(N_ET + 255)/256, 256, 0, s_side>>>(dst_idx);
    k_scan<<<1, 1024, 0, s_side>>>();
    k_scatter<<<(N_ET + 255)/256, 256, 0, s_side>>>(src_idx, dst_idx);
    cudaEventRecord(ev_join, s_side);

    k_gemm1_mma<<<G1_BLOCKS, 128, G1_SMEM>>>(x, W1, asrc1, adst1);

    // join: fused edge1 needs both gemm1 (main) and CSR (side)
    cudaStreamWaitEvent(0, ev_join, 0);

    k_edge1_fused<<<(N_NODES*32 + 255)/256, 256>>>(b1, W2, asrc2, adst2);
    k_edge2_csr<<<(N_NODES*32 + 255)/256, 256>>>(out, b2);
}